// round 11
// baseline (speedup 1.0000x reference)
#include <cuda_runtime.h>
#include <math.h>

#define Dm    256
#define D4    64                 // Dm / 4
#define Lw    32
#define Mm    4096
#define Cc    4096
#define NROWS (Mm + 1)           // 4097 memory rows (mems + appended xs)
#define NBW   128                // blocks in fused attention-weighted pass
#define WPB   8                  // warps per block in cosw
#define TOTW  (NBW * WPB)        // 1024 warps total
#define NFB   64                 // finish-kernel blocks
#define RPB   65                 // rows per finish block (64*65 >= 4097)
#define EPSV  1e-8f

// ---- scratch (__device__ globals; no allocation allowed) ----
__device__ float g_mems_enc[(size_t)NROWS * Dm];   // 4.2 MB encoded memories (+xs at row Mm)
__device__ float g_partial[NBW * Dm];              // per-block weighted partial sums (128 KB)
__device__ float g_attpart[NBW];                   // per-block exp-sum partials

__inline__ __device__ float warpReduceSum(float v) {
#pragma unroll
    for (int o = 16; o > 0; o >>= 1) v += __shfl_xor_sync(0xffffffffu, v, o);
    return v;
}

// ============================================================================
// Kernel 1: encoder, float4-vectorized. 64 threads/block, one block per row.
//   bid 0          : xs    -> g_mems_enc row Mm
//   bid 1..Mm      : mems  -> g_mems_enc rows 0..Mm-1
//   bid Mm+1       : ys    -> outY row 0
//   bid Mm+2..     : cands -> outY rows 1..Cc
// out = (1/||w||) * sum_l freqs[tok_l] * lt[tok_l][:]
// ============================================================================
__global__ void __launch_bounds__(D4) encode_kernel(
        const int* __restrict__ xs,   const int* __restrict__ mems,
        const int* __restrict__ ys,   const int* __restrict__ cands,
        const float4* __restrict__ lt4, const float* __restrict__ freqs,
        float4* __restrict__ outY4) {
    __shared__ int   stok[Lw];
    __shared__ float sw[Lw];
    __shared__ float sinv;

    const int bid = blockIdx.x;
    const int t   = threadIdx.x;            // 0..63 : float4 column
    const int* tok;
    float4* dst;
    float4* enc4 = (float4*)g_mems_enc;
    if (bid == 0)            { tok = xs;                            dst = enc4 + (size_t)Mm * D4; }
    else if (bid <= Mm)      { tok = mems  + (bid - 1) * Lw;        dst = enc4 + (size_t)(bid - 1) * D4; }
    else if (bid == Mm + 1)  { tok = ys;                            dst = outY4; }
    else                     { tok = cands + (bid - (Mm + 2)) * Lw; dst = outY4 + (size_t)(bid - (Mm + 1)) * D4; }

    if (t < Lw) {
        int   tk = tok[t];
        float w  = freqs[tk];
        stok[t] = tk;
        sw[t]   = w;
        float s = warpReduceSum(w * w);
        if (t == 0) sinv = 1.0f / sqrtf(s);
    }
    __syncthreads();

    float4 acc = make_float4(0.f, 0.f, 0.f, 0.f);
#pragma unroll
    for (int l = 0; l < Lw; ++l) {
        float  w = sw[l];
        float4 v = __ldg(&lt4[(size_t)stok[l] * D4 + t]);
        acc.x = fmaf(w, v.x, acc.x);
        acc.y = fmaf(w, v.y, acc.y);
        acc.z = fmaf(w, v.z, acc.z);
        acc.w = fmaf(w, v.w, acc.w);
    }
    const float s = sinv;
    acc.x *= s; acc.y *= s; acc.z *= s; acc.w *= s;
    dst[t] = acc;
}

// ============================================================================
// Kernel 2 (fused, warp-per-row): cosine + exp + attention-weighted partials.
// 8 warps/block; warp g = b*WPB + w owns rows {g, g+TOTW, ...} (deterministic
// fixed order). Each lane holds 8 dims (two float4 at cols lane, lane+32).
// All reductions are warp shuffles — no __syncthreads in the row loop.
// cos in [-1,1] so exp needs no max-subtraction; denominator folded into the
// finish kernel. Block epilogue: fixed-order 8-warp combine via smem.
// ============================================================================
__global__ void __launch_bounds__(256) cosw_kernel() {
    const int b    = blockIdx.x;
    const int t    = threadIdx.x;
    const int w    = t >> 5;
    const int lane = t & 31;
    const int g    = b * WPB + w;           // global warp id 0..TOTW-1

    const float4* enc4 = (const float4*)g_mems_enc;

    // xs_emb: each lane holds float4 cols lane and lane+32
    float4 a0 = enc4[(size_t)Mm * D4 + lane];
    float4 a1 = enc4[(size_t)Mm * D4 + lane + 32];
    float an;
    {
        float a2 = a0.x*a0.x + a0.y*a0.y + a0.z*a0.z + a0.w*a0.w
                 + a1.x*a1.x + a1.y*a1.y + a1.z*a1.z + a1.w*a1.w;
        a2 = warpReduceSum(a2);
        an = fmaxf(sqrtf(a2), EPSV);
    }

    float4 acc0 = make_float4(0.f,0.f,0.f,0.f);
    float4 acc1 = make_float4(0.f,0.f,0.f,0.f);
    float  esum = 0.0f;

    for (int i = g; i < NROWS; i += TOTW) {
        float4 v0 = enc4[(size_t)i * D4 + lane];
        float4 v1 = enc4[(size_t)i * D4 + lane + 32];
        float dot = a0.x*v0.x + a0.y*v0.y + a0.z*v0.z + a0.w*v0.w
                  + a1.x*v1.x + a1.y*v1.y + a1.z*v1.z + a1.w*v1.w;
        float b2  = v0.x*v0.x + v0.y*v0.y + v0.z*v0.z + v0.w*v0.w
                  + v1.x*v1.x + v1.y*v1.y + v1.z*v1.z + v1.w*v1.w;
        dot = warpReduceSum(dot);
        b2  = warpReduceSum(b2);
        float bn = fmaxf(sqrtf(b2), EPSV);
        float e  = __expf(dot / (an * bn));
        acc0.x = fmaf(e, v0.x, acc0.x); acc0.y = fmaf(e, v0.y, acc0.y);
        acc0.z = fmaf(e, v0.z, acc0.z); acc0.w = fmaf(e, v0.w, acc0.w);
        acc1.x = fmaf(e, v1.x, acc1.x); acc1.y = fmaf(e, v1.y, acc1.y);
        acc1.z = fmaf(e, v1.z, acc1.z); acc1.w = fmaf(e, v1.w, acc1.w);
        esum += e;
    }

    // block combine: 8 warps -> one partial row, fixed order (deterministic)
    __shared__ float4 sacc[WPB][2][32];     // 8 KB
    __shared__ float  ses[WPB];
    sacc[w][0][lane] = acc0;
    sacc[w][1][lane] = acc1;
    if (lane == 0) ses[w] = esum;
    __syncthreads();

    // thread t handles float4 column c = t & 63 (threads 64..255 idle-redundant)
    const int c  = t & 63;
    const int hh = (c >= 32) ? 1 : 0;
    const int ll = c & 31;
    float4 tot = make_float4(0.f,0.f,0.f,0.f);
#pragma unroll
    for (int k = 0; k < WPB; ++k) {
        float4 p = sacc[k][hh][ll];
        tot.x += p.x; tot.y += p.y; tot.z += p.z; tot.w += p.w;
    }
    if (t < 64) {
        ((float4*)g_partial)[b * D4 + c] = tot;
    }
    if (t == 0) {
        float es = 0.f;
#pragma unroll
        for (int k = 0; k < WPB; ++k) es += ses[k];
        g_attpart[b] = es;
    }
}

// ============================================================================
// Kernel 3 (finish): every block redundantly reduces the NBW x 256 partial
// matrix in FIXED order (identical result in all blocks, deterministic),
// computes lhs = colsum / sum(exp), then streams its 65-row slice of xs_out.
// Redundant reads: 64 blocks x 128 KB = 8.4 MB, all L2 hits.
// ============================================================================
__global__ void __launch_bounds__(256) finish_kernel(float4* __restrict__ outX4) {
    const int b = blockIdx.x;
    const int t = threadIdx.x;
    __shared__ float swarp[8];
    __shared__ float s_att;
    __shared__ float slhs[Dm];

    // denominator: reduce g_attpart[0..NBW-1], fixed tree order
    {
        float ap = (t < NBW) ? g_attpart[t] : 0.0f;
        ap = warpReduceSum(ap);
        if ((t & 31) == 0) swarp[t >> 5] = ap;
        __syncthreads();
        if (t == 0) {
            float s = swarp[0] + swarp[1] + swarp[2] + swarp[3];
            s_att = s;
        }
        __syncthreads();
    }

    // column sums over NBW partial rows, fixed ascending order per dim t
    float s = 0.0f;
#pragma unroll 8
    for (int bb = 0; bb < NBW; ++bb)
        s += g_partial[bb * Dm + t];
    slhs[t] = s / s_att;
    __syncthreads();

    // load the final row into a per-thread register float4 (column t & 63)
    const int c = t & 63;
    const float4 v = make_float4(slhs[4*c], slhs[4*c+1], slhs[4*c+2], slhs[4*c+3]);

    // write 65 rows: 4 rows per iteration (t>>6 = row-in-group)
    const int r0  = b * RPB + (t >> 6);
    const int rend = (b + 1) * RPB;
#pragma unroll 4
    for (int r = r0; r < rend; r += 4) {
        if (r < NROWS) outX4[(size_t)r * D4 + c] = v;
    }
}

extern "C" void kernel_launch(void* const* d_in, const int* in_sizes, int n_in,
                              void* d_out, int out_size) {
    const int*    xs    = (const int*)d_in[0];
    const int*    mems  = (const int*)d_in[1];
    const int*    ys    = (const int*)d_in[2];
    const int*    cands = (const int*)d_in[3];
    const float4* lt4   = (const float4*)d_in[4];
    const float*  freqs = (const float*)d_in[5];

    float*  out   = (float*)d_out;                        // xs_out first
    float4* outY4 = (float4*)(out + (size_t)NROWS * Dm);  // then ys_out

    encode_kernel<<<2 + Mm + Cc, D4>>>(xs, mems, ys, cands, lt4, freqs, outY4);
    cosw_kernel<<<NBW, 256>>>();
    finish_kernel<<<NFB, 256>>>((float4*)out);
}

// round 14
// speedup vs baseline: 1.0154x; 1.0154x over previous
#include <cuda_runtime.h>
#include <math.h>

#define Dm    256
#define D4    64                 // Dm / 4
#define Lw    32
#define Mm    4096
#define Cc    4096
#define NTOT  (2 + Mm + Cc)      // 8194 rows to encode
#define NROWS (Mm + 1)           // 4097 memory rows (mems + appended xs)
#define RPBE  4                  // rows per encode block
#define NBW   256                // blocks in fused attention-weighted pass
#define WPB   8                  // warps per block in cosw
#define TOTW  (NBW * WPB)        // 2048 warps total
#define EPSV  1e-8f

// ---- scratch (__device__ globals; no allocation allowed) ----
__device__ float g_mems_enc[(size_t)NROWS * Dm];   // 4.2 MB encoded memories (+xs at row Mm)
__device__ float g_partial[NBW * Dm];              // per-block weighted partial sums
__device__ float g_attpart[NBW];                   // per-block exp-sum partials
__device__ float g_lhs[Dm];                        // final attention-weighted vector

__inline__ __device__ float warpReduceSum(float v) {
#pragma unroll
    for (int o = 16; o > 0; o >>= 1) v += __shfl_xor_sync(0xffffffffu, v, o);
    return v;
}

// ============================================================================
// Kernel 1: encoder, 4 rows per 256-thread block (64-thread group per row).
// Group g handles linear row j = bid*4 + g:
//   j == 0          : xs    -> g_mems_enc row Mm
//   j in 1..Mm      : mems  -> g_mems_enc rows 0..Mm-1
//   j == Mm+1       : ys    -> outY row 0
//   j in Mm+2..     : cands -> outY rows 1..Cc
// out = (1/||w||) * sum_l freqs[tok_l] * lt[tok_l][:]
// 8 warps/CTA -> full warp residency at 8 CTAs/SM (was 2 warps/CTA needing
// all 32 CTA slots); same per-thread MLP (32 independent LDG.128).
// ============================================================================
__global__ void __launch_bounds__(256) encode_kernel(
        const int* __restrict__ xs,   const int* __restrict__ mems,
        const int* __restrict__ ys,   const int* __restrict__ cands,
        const float4* __restrict__ lt4, const float* __restrict__ freqs,
        float4* __restrict__ outY4) {
    __shared__ int   stok[RPBE][Lw];
    __shared__ float sw[RPBE][Lw];
    __shared__ float sinv[RPBE];

    const int t = threadIdx.x;
    const int g = t >> 6;                  // group 0..3 (one row each)
    const int c = t & 63;                  // float4 column 0..63
    const int j = blockIdx.x * RPBE + g;   // linear row id
    const bool active = (j < NTOT);

    const int* tok = xs;                   // safe defaults
    float4* dst = (float4*)g_mems_enc;
    float4* enc4 = (float4*)g_mems_enc;
    if (active) {
        if (j == 0)            { tok = xs;                          dst = enc4 + (size_t)Mm * D4; }
        else if (j <= Mm)      { tok = mems  + (j - 1) * Lw;        dst = enc4 + (size_t)(j - 1) * D4; }
        else if (j == Mm + 1)  { tok = ys;                          dst = outY4; }
        else                   { tok = cands + (j - (Mm + 2)) * Lw; dst = outY4 + (size_t)(j - (Mm + 1)) * D4; }
    }

    // c<32 selects the full even warp of each group -> valid full-warp shuffle
    if (active && c < Lw) {
        int   tk = tok[c];
        float w  = freqs[tk];
        stok[g][c] = tk;
        sw[g][c]   = w;
        float s = warpReduceSum(w * w);
        if (c == 0) sinv[g] = 1.0f / sqrtf(s);
    }
    __syncthreads();

    if (!active) return;

    float4 acc = make_float4(0.f, 0.f, 0.f, 0.f);
#pragma unroll
    for (int l = 0; l < Lw; ++l) {
        float  w = sw[g][l];
        float4 v = __ldg(&lt4[(size_t)stok[g][l] * D4 + c]);
        acc.x = fmaf(w, v.x, acc.x);
        acc.y = fmaf(w, v.y, acc.y);
        acc.z = fmaf(w, v.z, acc.z);
        acc.w = fmaf(w, v.w, acc.w);
    }
    const float s = sinv[g];
    acc.x *= s; acc.y *= s; acc.z *= s; acc.w *= s;
    dst[c] = acc;
}

// ============================================================================
// Kernel 2 (fused, warp-per-row): cosine + exp + attention-weighted partials.
// 8 warps/block; warp g = b*WPB + w owns rows {g, g+TOTW, ...} (deterministic
// fixed order). Each lane holds 8 dims (two float4 at cols lane, lane+32).
// All reductions are warp shuffles — no __syncthreads in the row loop.
// cos in [-1,1] so exp needs no max-subtraction; denominator folded into the
// final reduce. Block epilogue: fixed-order 8-warp combine via smem.
// ============================================================================
__global__ void __launch_bounds__(256) cosw_kernel() {
    const int b    = blockIdx.x;
    const int t    = threadIdx.x;
    const int w    = t >> 5;
    const int lane = t & 31;
    const int g    = b * WPB + w;           // global warp id 0..TOTW-1

    const float4* enc4 = (const float4*)g_mems_enc;

    // xs_emb: each lane holds float4 cols lane and lane+32
    float4 a0 = enc4[(size_t)Mm * D4 + lane];
    float4 a1 = enc4[(size_t)Mm * D4 + lane + 32];
    float an;
    {
        float a2 = a0.x*a0.x + a0.y*a0.y + a0.z*a0.z + a0.w*a0.w
                 + a1.x*a1.x + a1.y*a1.y + a1.z*a1.z + a1.w*a1.w;
        a2 = warpReduceSum(a2);
        an = fmaxf(sqrtf(a2), EPSV);
    }

    float4 acc0 = make_float4(0.f,0.f,0.f,0.f);
    float4 acc1 = make_float4(0.f,0.f,0.f,0.f);
    float  esum = 0.0f;

    for (int i = g; i < NROWS; i += TOTW) {
        float4 v0 = enc4[(size_t)i * D4 + lane];
        float4 v1 = enc4[(size_t)i * D4 + lane + 32];
        float dot = a0.x*v0.x + a0.y*v0.y + a0.z*v0.z + a0.w*v0.w
                  + a1.x*v1.x + a1.y*v1.y + a1.z*v1.z + a1.w*v1.w;
        float b2  = v0.x*v0.x + v0.y*v0.y + v0.z*v0.z + v0.w*v0.w
                  + v1.x*v1.x + v1.y*v1.y + v1.z*v1.z + v1.w*v1.w;
        dot = warpReduceSum(dot);
        b2  = warpReduceSum(b2);
        float bn = fmaxf(sqrtf(b2), EPSV);
        float e  = __expf(dot / (an * bn));
        acc0.x = fmaf(e, v0.x, acc0.x); acc0.y = fmaf(e, v0.y, acc0.y);
        acc0.z = fmaf(e, v0.z, acc0.z); acc0.w = fmaf(e, v0.w, acc0.w);
        acc1.x = fmaf(e, v1.x, acc1.x); acc1.y = fmaf(e, v1.y, acc1.y);
        acc1.z = fmaf(e, v1.z, acc1.z); acc1.w = fmaf(e, v1.w, acc1.w);
        esum += e;
    }

    // block combine: 8 warps -> one partial row, fixed order (deterministic)
    __shared__ float4 sacc[WPB][2][32];     // 8 KB
    __shared__ float  ses[WPB];
    sacc[w][0][lane] = acc0;
    sacc[w][1][lane] = acc1;
    if (lane == 0) ses[w] = esum;
    __syncthreads();

    // thread t handles float4 column c = t & 63 (threads 64..255 redundant)
    const int c  = t & 63;
    const int hh = (c >= 32) ? 1 : 0;
    const int ll = c & 31;
    float4 tot = make_float4(0.f,0.f,0.f,0.f);
#pragma unroll
    for (int k = 0; k < WPB; ++k) {
        float4 p = sacc[k][hh][ll];
        tot.x += p.x; tot.y += p.y; tot.z += p.z; tot.w += p.w;
    }
    if (t < 64) {
        ((float4*)g_partial)[b * D4 + c] = tot;
    }
    if (t == 0) {
        float es = 0.f;
#pragma unroll
        for (int k = 0; k < WPB; ++k) es += ses[k];
        g_attpart[b] = es;
    }
}

// ============================================================================
// Kernel 3: reduce NBW partials (fixed order) + denominator -> g_lhs.
// ============================================================================
__global__ void __launch_bounds__(1024) sumlhs_kernel() {
    const int t = threadIdx.x;
    __shared__ float ssum[8];
    __shared__ float s_att;
    __shared__ float spart[1024];

    float ap = (t < NBW) ? g_attpart[t] : 0.0f;
    ap = warpReduceSum(ap);
    if ((t & 31) == 0) ssum[t >> 5] = ap;
    __syncthreads();
    if (t == 0) {
        float s = 0.f;
#pragma unroll
        for (int k = 0; k < 8; ++k) s += ssum[k];
        s_att = s;
    }

    const int d = t & (Dm - 1);
    const int c = t >> 8;                   // 0..3
    float s = 0.0f;
#pragma unroll 8
    for (int bb = c; bb < NBW; bb += 4)
        s += g_partial[bb * Dm + d];
    spart[t] = s;
    __syncthreads();
    if (c == 0) {
        float tot = spart[d] + spart[256 + d] + spart[512 + d] + spart[768 + d];
        g_lhs[d] = tot / s_att;
    }
}

// ============================================================================
// Kernel 4: broadcast lhs into 4097 xs_out rows.
// Grid-stride of 65536 float4 (multiple of 64) => idx & 63 constant per
// thread: ONE g_lhs register load, then a pure STG.128 loop.
// ============================================================================
__global__ void __launch_bounds__(256) tile_kernel(float4* __restrict__ outX4) {
    const int tid   = blockIdx.x * blockDim.x + threadIdx.x;   // 0..65535
    const int total = NROWS * D4;                              // 262208
    const float4 v  = __ldg(&((const float4*)g_lhs)[tid & (D4 - 1)]);
#pragma unroll 4
    for (int idx = tid; idx < total; idx += 256 * 256)
        outX4[idx] = v;
}

extern "C" void kernel_launch(void* const* d_in, const int* in_sizes, int n_in,
                              void* d_out, int out_size) {
    const int*    xs    = (const int*)d_in[0];
    const int*    mems  = (const int*)d_in[1];
    const int*    ys    = (const int*)d_in[2];
    const int*    cands = (const int*)d_in[3];
    const float4* lt4   = (const float4*)d_in[4];
    const float*  freqs = (const float*)d_in[5];

    float*  out   = (float*)d_out;                        // xs_out first
    float4* outY4 = (float4*)(out + (size_t)NROWS * Dm);  // then ys_out

    encode_kernel<<<(NTOT + RPBE - 1) / RPBE, 256>>>(xs, mems, ys, cands, lt4, freqs, outY4);
    cosw_kernel<<<NBW, 256>>>();
    sumlhs_kernel<<<1, 1024>>>();
    tile_kernel<<<256, 256>>>((float4*)out);
}

// round 15
// speedup vs baseline: 1.0752x; 1.0589x over previous
#include <cuda_runtime.h>
#include <math.h>

#define Dm    256
#define D4    64                 // Dm / 4
#define Lw    32
#define Mm    4096
#define Cc    4096
#define NTOT  (2 + Mm + Cc)      // 8194 rows to encode
#define NROWS (Mm + 1)           // 4097 memory rows (mems + appended xs)
#define NBW   256                // blocks in fused attention-weighted pass
#define WPB   8                  // warps per block in cosw
#define TOTW  (NBW * WPB)        // 2048 warps total
#define EPSV  1e-8f

// ---- scratch (__device__ globals; no allocation allowed) ----
__device__ float g_mems_enc[(size_t)NROWS * Dm];   // 4.2 MB encoded memories (+xs at row Mm)
__device__ float g_partial[NBW * Dm];              // per-block weighted partial sums
__device__ float g_attpart[NBW];                   // per-block exp-sum partials
__device__ float g_lhs[Dm];                        // final attention-weighted vector

__inline__ __device__ float warpReduceSum(float v) {
#pragma unroll
    for (int o = 16; o > 0; o >>= 1) v += __shfl_xor_sync(0xffffffffu, v, o);
    return v;
}

// ============================================================================
// Kernel 1: encoder. 64 threads/block, one block per row (R10 shape).
// Inner loop restructured into TWO 16-deep explicit load batches: 16 float4
// in registers before consuming -> per-thread MLP ~16 (was ~5 at regs=34),
// closing the latency gap to the LTS cap. Accumulation order l=0..31 is
// unchanged (batch 0..15 then 16..31) -> bitwise-identical output.
//   bid 0          : xs    -> g_mems_enc row Mm
//   bid 1..Mm      : mems  -> g_mems_enc rows 0..Mm-1
//   bid Mm+1       : ys    -> outY row 0
//   bid Mm+2..     : cands -> outY rows 1..Cc
// ============================================================================
__global__ void __launch_bounds__(D4) encode_kernel(
        const int* __restrict__ xs,   const int* __restrict__ mems,
        const int* __restrict__ ys,   const int* __restrict__ cands,
        const float4* __restrict__ lt4, const float* __restrict__ freqs,
        float4* __restrict__ outY4) {
    __shared__ int   stok[Lw];
    __shared__ float sw[Lw];
    __shared__ float sinv;

    const int bid = blockIdx.x;
    const int t   = threadIdx.x;            // 0..63 : float4 column
    const int* tok;
    float4* dst;
    float4* enc4 = (float4*)g_mems_enc;
    if (bid == 0)            { tok = xs;                            dst = enc4 + (size_t)Mm * D4; }
    else if (bid <= Mm)      { tok = mems  + (bid - 1) * Lw;        dst = enc4 + (size_t)(bid - 1) * D4; }
    else if (bid == Mm + 1)  { tok = ys;                            dst = outY4; }
    else                     { tok = cands + (bid - (Mm + 2)) * Lw; dst = outY4 + (size_t)(bid - (Mm + 1)) * D4; }

    if (t < Lw) {
        int   tk = tok[t];
        float w  = freqs[tk];
        stok[t] = tk;
        sw[t]   = w;
        float s = warpReduceSum(w * w);
        if (t == 0) sinv = 1.0f / sqrtf(s);
    }
    __syncthreads();

    float4 acc = make_float4(0.f, 0.f, 0.f, 0.f);
#pragma unroll
    for (int base = 0; base < Lw; base += 16) {
        float4 v[16];
#pragma unroll
        for (int k = 0; k < 16; ++k)
            v[k] = __ldg(&lt4[(size_t)stok[base + k] * D4 + t]);
#pragma unroll
        for (int k = 0; k < 16; ++k) {
            const float w = sw[base + k];
            acc.x = fmaf(w, v[k].x, acc.x);
            acc.y = fmaf(w, v[k].y, acc.y);
            acc.z = fmaf(w, v[k].z, acc.z);
            acc.w = fmaf(w, v[k].w, acc.w);
        }
    }
    const float s = sinv;
    acc.x *= s; acc.y *= s; acc.z *= s; acc.w *= s;
    dst[t] = acc;
}

// ============================================================================
// Kernel 2 (fused, warp-per-row): cosine + exp + attention-weighted partials.
// 8 warps/block; warp g = b*WPB + w owns rows {g, g+TOTW, ...} (deterministic
// fixed order). Each lane holds 8 dims (two float4 at cols lane, lane+32).
// All reductions are warp shuffles — no __syncthreads in the row loop.
// cos in [-1,1] so exp needs no max-subtraction; denominator folded into the
// final reduce. Block epilogue: fixed-order 8-warp combine via smem.
// ============================================================================
__global__ void __launch_bounds__(256) cosw_kernel() {
    const int b    = blockIdx.x;
    const int t    = threadIdx.x;
    const int w    = t >> 5;
    const int lane = t & 31;
    const int g    = b * WPB + w;           // global warp id 0..TOTW-1

    const float4* enc4 = (const float4*)g_mems_enc;

    // xs_emb: each lane holds float4 cols lane and lane+32
    float4 a0 = enc4[(size_t)Mm * D4 + lane];
    float4 a1 = enc4[(size_t)Mm * D4 + lane + 32];
    float an;
    {
        float a2 = a0.x*a0.x + a0.y*a0.y + a0.z*a0.z + a0.w*a0.w
                 + a1.x*a1.x + a1.y*a1.y + a1.z*a1.z + a1.w*a1.w;
        a2 = warpReduceSum(a2);
        an = fmaxf(sqrtf(a2), EPSV);
    }

    float4 acc0 = make_float4(0.f,0.f,0.f,0.f);
    float4 acc1 = make_float4(0.f,0.f,0.f,0.f);
    float  esum = 0.0f;

    for (int i = g; i < NROWS; i += TOTW) {
        float4 v0 = enc4[(size_t)i * D4 + lane];
        float4 v1 = enc4[(size_t)i * D4 + lane + 32];
        float dot = a0.x*v0.x + a0.y*v0.y + a0.z*v0.z + a0.w*v0.w
                  + a1.x*v1.x + a1.y*v1.y + a1.z*v1.z + a1.w*v1.w;
        float b2  = v0.x*v0.x + v0.y*v0.y + v0.z*v0.z + v0.w*v0.w
                  + v1.x*v1.x + v1.y*v1.y + v1.z*v1.z + v1.w*v1.w;
        dot = warpReduceSum(dot);
        b2  = warpReduceSum(b2);
        float bn = fmaxf(sqrtf(b2), EPSV);
        float e  = __expf(dot / (an * bn));
        acc0.x = fmaf(e, v0.x, acc0.x); acc0.y = fmaf(e, v0.y, acc0.y);
        acc0.z = fmaf(e, v0.z, acc0.z); acc0.w = fmaf(e, v0.w, acc0.w);
        acc1.x = fmaf(e, v1.x, acc1.x); acc1.y = fmaf(e, v1.y, acc1.y);
        acc1.z = fmaf(e, v1.z, acc1.z); acc1.w = fmaf(e, v1.w, acc1.w);
        esum += e;
    }

    // block combine: 8 warps -> one partial row, fixed order (deterministic)
    __shared__ float4 sacc[WPB][2][32];     // 8 KB
    __shared__ float  ses[WPB];
    sacc[w][0][lane] = acc0;
    sacc[w][1][lane] = acc1;
    if (lane == 0) ses[w] = esum;
    __syncthreads();

    // thread t handles float4 column c = t & 63 (threads 64..255 redundant)
    const int c  = t & 63;
    const int hh = (c >= 32) ? 1 : 0;
    const int ll = c & 31;
    float4 tot = make_float4(0.f,0.f,0.f,0.f);
#pragma unroll
    for (int k = 0; k < WPB; ++k) {
        float4 p = sacc[k][hh][ll];
        tot.x += p.x; tot.y += p.y; tot.z += p.z; tot.w += p.w;
    }
    if (t < 64) {
        ((float4*)g_partial)[b * D4 + c] = tot;
    }
    if (t == 0) {
        float es = 0.f;
#pragma unroll
        for (int k = 0; k < WPB; ++k) es += ses[k];
        g_attpart[b] = es;
    }
}

// ============================================================================
// Kernel 3: reduce NBW partials (fixed order) + denominator -> g_lhs.
// ============================================================================
__global__ void __launch_bounds__(1024) sumlhs_kernel() {
    const int t = threadIdx.x;
    __shared__ float ssum[8];
    __shared__ float s_att;
    __shared__ float spart[1024];

    float ap = (t < NBW) ? g_attpart[t] : 0.0f;
    ap = warpReduceSum(ap);
    if ((t & 31) == 0) ssum[t >> 5] = ap;
    __syncthreads();
    if (t == 0) {
        float s = 0.f;
#pragma unroll
        for (int k = 0; k < 8; ++k) s += ssum[k];
        s_att = s;
    }

    const int d = t & (Dm - 1);
    const int c = t >> 8;                   // 0..3
    float s = 0.0f;
#pragma unroll 8
    for (int bb = c; bb < NBW; bb += 4)
        s += g_partial[bb * Dm + d];
    spart[t] = s;
    __syncthreads();
    if (c == 0) {
        float tot = spart[d] + spart[256 + d] + spart[512 + d] + spart[768 + d];
        g_lhs[d] = tot / s_att;
    }
}

// ============================================================================
// Kernel 4: broadcast lhs into 4097 xs_out rows.
// Grid-stride of 65536 float4 (multiple of 64) => idx & 63 constant per
// thread: ONE g_lhs register load, then a pure STG.128 loop.
// ============================================================================
__global__ void __launch_bounds__(256) tile_kernel(float4* __restrict__ outX4) {
    const int tid   = blockIdx.x * blockDim.x + threadIdx.x;   // 0..65535
    const int total = NROWS * D4;                              // 262208
    const float4 v  = __ldg(&((const float4*)g_lhs)[tid & (D4 - 1)]);
#pragma unroll 4
    for (int idx = tid; idx < total; idx += 256 * 256)
        outX4[idx] = v;
}

extern "C" void kernel_launch(void* const* d_in, const int* in_sizes, int n_in,
                              void* d_out, int out_size) {
    const int*    xs    = (const int*)d_in[0];
    const int*    mems  = (const int*)d_in[1];
    const int*    ys    = (const int*)d_in[2];
    const int*    cands = (const int*)d_in[3];
    const float4* lt4   = (const float4*)d_in[4];
    const float*  freqs = (const float*)d_in[5];

    float*  out   = (float*)d_out;                        // xs_out first
    float4* outY4 = (float4*)(out + (size_t)NROWS * Dm);  // then ys_out

    encode_kernel<<<NTOT, D4>>>(xs, mems, ys, cands, lt4, freqs, outY4);
    cosw_kernel<<<NBW, 256>>>();
    sumlhs_kernel<<<1, 1024>>>();
    tile_kernel<<<256, 256>>>((float4*)out);
}

// round 16
// speedup vs baseline: 1.0871x; 1.0110x over previous
#include <cuda_runtime.h>
#include <math.h>

#define Dm    256
#define D4    64                 // Dm / 4
#define Lw    32
#define Mm    4096
#define Cc    4096
#define NROWS (Mm + 1)           // 4097 memory rows (mems + appended xs)
#define NBW   256                // blocks in fused attention-weighted pass
#define WPB   8                  // warps per block in cosw
#define TOTW  (NBW * WPB)        // 2048 warps total
#define EPSV  1e-8f

// ---- scratch (__device__ globals; no allocation allowed) ----
__device__ float g_mems_enc[(size_t)NROWS * Dm];   // 4.2 MB encoded memories (+xs at row Mm)
__device__ float g_partial[NBW * Dm];              // per-block weighted partial sums
__device__ float g_attpart[NBW];                   // per-block exp-sum partials
__device__ float g_lhs[Dm];                        // final attention-weighted vector

__inline__ __device__ float warpReduceSum(float v) {
#pragma unroll
    for (int o = 16; o > 0; o >>= 1) v += __shfl_xor_sync(0xffffffffu, v, o);
    return v;
}

// ---- shared encoder body: one 64-thread block encodes one row ----
__device__ __forceinline__ void encode_row(const int* __restrict__ tok,
                                           const float4* __restrict__ lt4,
                                           const float* __restrict__ freqs,
                                           float4* __restrict__ dst) {
    __shared__ int   stok[Lw];
    __shared__ float sw[Lw];
    __shared__ float sinv;

    const int t = threadIdx.x;              // 0..63 : float4 column
    if (t < Lw) {
        int   tk = tok[t];
        float w  = freqs[tk];
        stok[t] = tk;
        sw[t]   = w;
        float s = warpReduceSum(w * w);
        if (t == 0) sinv = 1.0f / sqrtf(s);
    }
    __syncthreads();

    float4 acc = make_float4(0.f, 0.f, 0.f, 0.f);
#pragma unroll
    for (int base = 0; base < Lw; base += 16) {
        float4 v[16];
#pragma unroll
        for (int k = 0; k < 16; ++k)
            v[k] = __ldg(&lt4[(size_t)stok[base + k] * D4 + t]);
#pragma unroll
        for (int k = 0; k < 16; ++k) {
            const float w = sw[base + k];
            acc.x = fmaf(w, v[k].x, acc.x);
            acc.y = fmaf(w, v[k].y, acc.y);
            acc.z = fmaf(w, v[k].z, acc.z);
            acc.w = fmaf(w, v[k].w, acc.w);
        }
    }
    const float s = sinv;
    acc.x *= s; acc.y *= s; acc.z *= s; acc.w *= s;
    dst[t] = acc;
}

// ============================================================================
// Kernel 1a: encode xs + mems -> g_mems_enc (tail branch root).
//   bid 0      : xs   -> row Mm
//   bid 1..Mm  : mems -> rows 0..Mm-1
// ============================================================================
__global__ void __launch_bounds__(D4) encode_mx_kernel(
        const int* __restrict__ xs, const int* __restrict__ mems,
        const float4* __restrict__ lt4, const float* __restrict__ freqs) {
    const int bid = blockIdx.x;
    float4* enc4 = (float4*)g_mems_enc;
    const int* tok = (bid == 0) ? xs : (mems + (bid - 1) * Lw);
    float4*    dst = (bid == 0) ? (enc4 + (size_t)Mm * D4)
                                : (enc4 + (size_t)(bid - 1) * D4);
    encode_row(tok, lt4, freqs, dst);
}

// ============================================================================
// Kernel 1b: encode ys + cands -> outY directly (independent branch).
//   bid 0      : ys    -> outY row 0
//   bid 1..Cc  : cands -> outY rows 1..Cc
// ============================================================================
__global__ void __launch_bounds__(D4) encode_yc_kernel(
        const int* __restrict__ ys, const int* __restrict__ cands,
        const float4* __restrict__ lt4, const float* __restrict__ freqs,
        float4* __restrict__ outY4) {
    const int bid = blockIdx.x;
    const int* tok = (bid == 0) ? ys : (cands + (bid - 1) * Lw);
    float4*    dst = outY4 + (size_t)bid * D4;
    encode_row(tok, lt4, freqs, dst);
}

// ============================================================================
// Kernel 2 (fused, warp-per-row): cosine + exp + attention-weighted partials.
// 8 warps/block; warp g = b*WPB + w owns rows {g, g+TOTW, ...} (deterministic
// fixed order). Each lane holds 8 dims (two float4 at cols lane, lane+32).
// All reductions are warp shuffles — no __syncthreads in the row loop.
// cos in [-1,1] so exp needs no max-subtraction; denominator folded into the
// final reduce. Block epilogue: fixed-order 8-warp combine via smem.
// ============================================================================
__global__ void __launch_bounds__(256) cosw_kernel() {
    const int b    = blockIdx.x;
    const int t    = threadIdx.x;
    const int w    = t >> 5;
    const int lane = t & 31;
    const int g    = b * WPB + w;           // global warp id 0..TOTW-1

    const float4* enc4 = (const float4*)g_mems_enc;

    float4 a0 = enc4[(size_t)Mm * D4 + lane];
    float4 a1 = enc4[(size_t)Mm * D4 + lane + 32];
    float an;
    {
        float a2 = a0.x*a0.x + a0.y*a0.y + a0.z*a0.z + a0.w*a0.w
                 + a1.x*a1.x + a1.y*a1.y + a1.z*a1.z + a1.w*a1.w;
        a2 = warpReduceSum(a2);
        an = fmaxf(sqrtf(a2), EPSV);
    }

    float4 acc0 = make_float4(0.f,0.f,0.f,0.f);
    float4 acc1 = make_float4(0.f,0.f,0.f,0.f);
    float  esum = 0.0f;

    for (int i = g; i < NROWS; i += TOTW) {
        float4 v0 = enc4[(size_t)i * D4 + lane];
        float4 v1 = enc4[(size_t)i * D4 + lane + 32];
        float dot = a0.x*v0.x + a0.y*v0.y + a0.z*v0.z + a0.w*v0.w
                  + a1.x*v1.x + a1.y*v1.y + a1.z*v1.z + a1.w*v1.w;
        float b2  = v0.x*v0.x + v0.y*v0.y + v0.z*v0.z + v0.w*v0.w
                  + v1.x*v1.x + v1.y*v1.y + v1.z*v1.z + v1.w*v1.w;
        dot = warpReduceSum(dot);
        b2  = warpReduceSum(b2);
        float bn = fmaxf(sqrtf(b2), EPSV);
        float e  = __expf(dot / (an * bn));
        acc0.x = fmaf(e, v0.x, acc0.x); acc0.y = fmaf(e, v0.y, acc0.y);
        acc0.z = fmaf(e, v0.z, acc0.z); acc0.w = fmaf(e, v0.w, acc0.w);
        acc1.x = fmaf(e, v1.x, acc1.x); acc1.y = fmaf(e, v1.y, acc1.y);
        acc1.z = fmaf(e, v1.z, acc1.z); acc1.w = fmaf(e, v1.w, acc1.w);
        esum += e;
    }

    __shared__ float4 sacc[WPB][2][32];     // 8 KB
    __shared__ float  ses[WPB];
    sacc[w][0][lane] = acc0;
    sacc[w][1][lane] = acc1;
    if (lane == 0) ses[w] = esum;
    __syncthreads();

    const int c  = t & 63;
    const int hh = (c >= 32) ? 1 : 0;
    const int ll = c & 31;
    float4 tot = make_float4(0.f,0.f,0.f,0.f);
#pragma unroll
    for (int k = 0; k < WPB; ++k) {
        float4 p = sacc[k][hh][ll];
        tot.x += p.x; tot.y += p.y; tot.z += p.z; tot.w += p.w;
    }
    if (t < 64) {
        ((float4*)g_partial)[b * D4 + c] = tot;
    }
    if (t == 0) {
        float es = 0.f;
#pragma unroll
        for (int k = 0; k < WPB; ++k) es += ses[k];
        g_attpart[b] = es;
    }
}

// ============================================================================
// Kernel 3: reduce NBW partials (fixed order) + denominator -> g_lhs.
// ============================================================================
__global__ void __launch_bounds__(1024) sumlhs_kernel() {
    const int t = threadIdx.x;
    __shared__ float ssum[8];
    __shared__ float s_att;
    __shared__ float spart[1024];

    float ap = (t < NBW) ? g_attpart[t] : 0.0f;
    ap = warpReduceSum(ap);
    if ((t & 31) == 0) ssum[t >> 5] = ap;
    __syncthreads();
    if (t == 0) {
        float s = 0.f;
#pragma unroll
        for (int k = 0; k < 8; ++k) s += ssum[k];
        s_att = s;
    }

    const int d = t & (Dm - 1);
    const int c = t >> 8;                   // 0..3
    float s = 0.0f;
#pragma unroll 8
    for (int bb = c; bb < NBW; bb += 4)
        s += g_partial[bb * Dm + d];
    spart[t] = s;
    __syncthreads();
    if (c == 0) {
        float tot = spart[d] + spart[256 + d] + spart[512 + d] + spart[768 + d];
        g_lhs[d] = tot / s_att;
    }
}

// ============================================================================
// Kernel 4: broadcast lhs into 4097 xs_out rows (idx & 63 constant/thread ->
// one register load, then pure STG.128 loop).
// ============================================================================
__global__ void __launch_bounds__(256) tile_kernel(float4* __restrict__ outX4) {
    const int tid   = blockIdx.x * blockDim.x + threadIdx.x;   // 0..65535
    const int total = NROWS * D4;                              // 262208
    const float4 v  = __ldg(&((const float4*)g_lhs)[tid & (D4 - 1)]);
#pragma unroll 4
    for (int idx = tid; idx < total; idx += 256 * 256)
        outX4[idx] = v;
}

extern "C" void kernel_launch(void* const* d_in, const int* in_sizes, int n_in,
                              void* d_out, int out_size) {
    const int*    xs    = (const int*)d_in[0];
    const int*    mems  = (const int*)d_in[1];
    const int*    ys    = (const int*)d_in[2];
    const int*    cands = (const int*)d_in[3];
    const float4* lt4   = (const float4*)d_in[4];
    const float*  freqs = (const float*)d_in[5];

    float*  out   = (float*)d_out;                        // xs_out first
    float4* outY4 = (float4*)(out + (size_t)NROWS * Dm);  // then ys_out

    // one-time host-side resources (no device memory involved)
    static cudaStream_t s2 = nullptr;
    static cudaEvent_t  eFork = nullptr, eJoin = nullptr;
    if (s2 == nullptr) {
        cudaStreamCreateWithFlags(&s2, cudaStreamNonBlocking);
        cudaEventCreateWithFlags(&eFork, cudaEventDisableTiming);
        cudaEventCreateWithFlags(&eJoin, cudaEventDisableTiming);
    }

    // fork: yc-encode branch runs concurrently with mx-encode + tail
    cudaEventRecord(eFork, 0);
    cudaStreamWaitEvent(s2, eFork, 0);
    encode_yc_kernel<<<1 + Cc, D4, 0, s2>>>(ys, cands, lt4, freqs, outY4);

    // main branch: mems+xs encode, then the dependent tail
    encode_mx_kernel<<<1 + Mm, D4>>>(xs, mems, lt4, freqs);
    cosw_kernel<<<NBW, 256>>>();
    sumlhs_kernel<<<1, 1024>>>();
    tile_kernel<<<256, 256>>>((float4*)out);

    // join: completion requires the yc branch too
    cudaEventRecord(eJoin, s2);
    cudaStreamWaitEvent(0, eJoin, 0);
}